// round 14
// baseline (speedup 1.0000x reference)
#include <cuda_runtime.h>
#include <cuda_fp16.h>
#include <cstdint>

// ----------------------------------------------------------------------------
// CrossAttention_30056181138117 on GB300 (sm_103a) — round 13
//
// (harness lowers through family-generic compute_103 PTX -> tcgen05 rejected;
// tuned legacy-HMMA path)
//
// Seq-len-1 attention => softmax == 1 => attn out == V projection, folded:
//   att_s = x_other @ Wc_s^T + c_s,  Wc_s = out_w_s @ wv_s
// Per stream: h = LN(x + att); u = relu(h@w1^T+b1); o = LN(h + u@w2^T+b2)
//
// Round-13: wide-tile GEMM (BM=64, BN=512, 512 threads, 16 warps, warp tile
// 32x64) with the PROVEN 3-stage/BK=32/LDS40/single-barrier mainloop.
//  * A operand read once per GEMM (was 4-8x)  -> ~0.9 GB less DRAM traffic
//  * LayerNorm fused into the GEMM epilogue (full row in CTA) -> t16 buffer
//    and all 4 k_ln launches eliminated (~256 MB + launch latency)
// Stream fork/join + fp16 residuals retained from the round-8 winner.
// ----------------------------------------------------------------------------

#define MROWS 32768
#define EDIM  512
#define FFDIM 1024

#define BM 64
#define BN 512
#define BK 32
#define NSTAGE 3
#define LDS 40                          // halfs per smem row (80B, 16B-aligned)
#define ASTG (BM * LDS)                 // 2560 halfs
#define WSTG (BN * LDS)                 // 20480 halfs
#define GEMM_SMEM (NSTAGE * (ASTG + WSTG) * 2)   // 138240 bytes

// ------------------------- device scratch (static, no allocs) ---------------
__device__ __half g_xh0[MROWS * EDIM];
__device__ __half g_xh1[MROWS * EDIM];
__device__ __half g_h  [2][MROWS * EDIM];
__device__ __half g_u  [2][MROWS * FFDIM];
__device__ __half g_wc [2 * EDIM * EDIM];
__device__ float  g_c  [2 * EDIM];
__device__ __half g_w1h[2 * FFDIM * EDIM];
__device__ __half g_w2h[2 * EDIM * FFDIM];

// ------------------------- helpers -------------------------------------------
__device__ __forceinline__ void cp_async16(uint32_t dst, const void* src) {
    asm volatile("cp.async.cg.shared.global [%0], [%1], 16;\n" :: "r"(dst), "l"(src));
}
__device__ __forceinline__ void ldsm_x4(uint32_t& r0, uint32_t& r1,
                                        uint32_t& r2, uint32_t& r3, uint32_t addr) {
    asm volatile("ldmatrix.sync.aligned.m8n8.x4.shared.b16 {%0,%1,%2,%3}, [%4];"
                 : "=r"(r0), "=r"(r1), "=r"(r2), "=r"(r3) : "r"(addr));
}

// ------------------------- small kernels -------------------------------------
__global__ void k_f2h(const float* __restrict__ src, __half* __restrict__ dst, int n) {
    int i = (blockIdx.x * blockDim.x + threadIdx.x) * 4;
    if (i >= n) return;
    float4 v = *(const float4*)(src + i);
    __half2* d = (__half2*)(dst + i);
    d[0] = __floats2half2_rn(v.x, v.y);
    d[1] = __floats2half2_rn(v.z, v.w);
}

__global__ void k_fold(const float* __restrict__ out_w,
                       const float* __restrict__ wv,
                       __half* __restrict__ wc) {
    __shared__ float srow[EDIM];
    int i = blockIdx.x, k = threadIdx.x;
    srow[k] = out_w[i * EDIM + k];
    __syncthreads();
    float acc = 0.f;
#pragma unroll 4
    for (int j = 0; j < EDIM; j++) acc = fmaf(srow[j], wv[j * EDIM + k], acc);
    wc[i * EDIM + k] = __float2half(acc);
}

__global__ void k_foldc(const float* __restrict__ out_w,
                        const float* __restrict__ out_b,
                        const float* __restrict__ bv,
                        float* __restrict__ c) {
    int i = blockIdx.x * blockDim.x + threadIdx.x;
    if (i >= EDIM) return;
    float acc = out_b[i];
    for (int j = 0; j < EDIM; j++) acc = fmaf(out_w[i * EDIM + j], bv[j], acc);
    c[i] = acc;
}

// ------------------------- wide fp16 HMMA GEMM (+fused LN) --------------------
// Tile 64x512, 512 threads, 16 warps (2 along M x 8 along N), warp tile 32x64.
// out[r][n] = sum_k A[r][k]*W[n][k] + bias (+relu) (+fp16 residual).
// DO_LN: LayerNorm over the 512-wide row fused in the epilogue.
template <int K, int DO_LN>
__global__ __launch_bounds__(512, 1) void k_gemm_w(
    const __half* __restrict__ A, const __half* __restrict__ W,
    const float* __restrict__ bias,
    const __half* __restrict__ resh,    // fp16 residual [M, EDIM] or null
    const float* __restrict__ gam, const float* __restrict__ bet,  // LN params
    __half* __restrict__ outh, int ostride,   // fp16 out (or null)
    float* __restrict__ outf, int ldo, int coloff,  // fp32 out (or null)
    int relu)
{
    constexpr int NT = K / BK;
    extern __shared__ __half smem[];
    __half* Asm = smem;
    __half* Wsm = smem + NSTAGE * ASTG;
    const uint32_t as_u = (uint32_t)__cvta_generic_to_shared(Asm);
    const uint32_t ws_u = (uint32_t)__cvta_generic_to_shared(Wsm);

    const int t = threadIdx.x;
    const int warp = t >> 5, lane = t & 31;
    const int g = lane >> 2, tg = lane & 3;
    const int brow = blockIdx.y * BM;
    const int bcol = blockIdx.x * BN;
    const int wm = (warp >> 3) * 32;    // 2 warps along M
    const int wn = (warp & 7) * 64;     // 8 warps along N
    const int wn8 = warp & 7;

    // load mapping: A by threads 0..255 (1 chunk), W by all 512 (4 chunks)
    const int lr = t >> 2;              // 0..127
    const int lc = (t & 3) * 8;
    const __half* Ag = A + (size_t)(brow + (lr & 63)) * K + lc;
    const __half* Wg = W + (size_t)(bcol + lr) * K + lc;

    const int arow = lane & 15;
    const int acol = (lane & 16) >> 1;
    const int browl = (lane & 7) + ((lane & 16) >> 1);
    const int bcoll = lane & 8;

    float acc[2][8][4];
#pragma unroll
    for (int a = 0; a < 2; a++)
#pragma unroll
        for (int b = 0; b < 8; b++)
#pragma unroll
            for (int c = 0; c < 4; c++) acc[a][b][c] = 0.f;

    auto load_stage = [&](int i, int slot) {
        const int ko = i * BK;
        const uint32_t as = as_u + slot * ASTG * 2;
        const uint32_t ws = ws_u + slot * WSTG * 2;
        if (t < 256)
            cp_async16(as + (lr * LDS + lc) * 2, Ag + ko);
#pragma unroll
        for (int r = 0; r < 4; r++)
            cp_async16(ws + ((lr + 128 * r) * LDS + lc) * 2,
                       Wg + ko + (size_t)(128 * r) * K);
        asm volatile("cp.async.commit_group;\n");
    };

    load_stage(0, 0);
    load_stage(1, 1);

    for (int i = 0; i < NT; i++) {
        if (i + 1 < NT) asm volatile("cp.async.wait_group 1;\n");
        else            asm volatile("cp.async.wait_group 0;\n");
        __syncthreads();   // single barrier per K-iter

        if (i + 2 < NT) load_stage(i + 2, (i + 2) % NSTAGE);

        const int s = i % NSTAGE;
        const uint32_t as = as_u + s * ASTG * 2;
        const uint32_t ws = ws_u + s * WSTG * 2;

#pragma unroll
        for (int kk = 0; kk < BK; kk += 16) {
            uint32_t ra[2][4], rb[8][2];
#pragma unroll
            for (int mi = 0; mi < 2; mi++)
                ldsm_x4(ra[mi][0], ra[mi][1], ra[mi][2], ra[mi][3],
                        as + ((wm + mi * 16 + arow) * LDS + kk + acol) * 2);
#pragma unroll
            for (int np = 0; np < 4; np++)
                ldsm_x4(rb[2 * np][0], rb[2 * np][1], rb[2 * np + 1][0], rb[2 * np + 1][1],
                        ws + ((wn + np * 16 + browl) * LDS + kk + bcoll) * 2);
#pragma unroll
            for (int mi = 0; mi < 2; mi++)
#pragma unroll
                for (int ni = 0; ni < 8; ni++)
                    asm volatile(
                        "mma.sync.aligned.m16n8k16.row.col.f32.f16.f16.f32 "
                        "{%0,%1,%2,%3}, {%4,%5,%6,%7}, {%8,%9}, {%0,%1,%2,%3};"
                        : "+f"(acc[mi][ni][0]), "+f"(acc[mi][ni][1]),
                          "+f"(acc[mi][ni][2]), "+f"(acc[mi][ni][3])
                        : "r"(ra[mi][0]), "r"(ra[mi][1]), "r"(ra[mi][2]), "r"(ra[mi][3]),
                          "r"(rb[ni][0]), "r"(rb[ni][1]));
        }
    }

    // ---- epilogue: bias (+relu) (+residual) into acc ----
#pragma unroll
    for (int mi = 0; mi < 2; mi++) {
#pragma unroll
        for (int ni = 0; ni < 8; ni++) {
            int r0 = brow + wm + mi * 16 + g;
            int r1 = r0 + 8;
            int c0 = bcol + wn + ni * 8 + tg * 2;
            float b0 = bias[c0], b1 = bias[c0 + 1];
            acc[mi][ni][0] += b0; acc[mi][ni][1] += b1;
            acc[mi][ni][2] += b0; acc[mi][ni][3] += b1;
            if (relu) {
                acc[mi][ni][0] = fmaxf(acc[mi][ni][0], 0.f);
                acc[mi][ni][1] = fmaxf(acc[mi][ni][1], 0.f);
                acc[mi][ni][2] = fmaxf(acc[mi][ni][2], 0.f);
                acc[mi][ni][3] = fmaxf(acc[mi][ni][3], 0.f);
            }
            if (resh) {
                float2 f0 = __half22float2(*(const __half2*)&resh[(size_t)r0 * EDIM + c0]);
                float2 f1 = __half22float2(*(const __half2*)&resh[(size_t)r1 * EDIM + c0]);
                acc[mi][ni][0] += f0.x; acc[mi][ni][1] += f0.y;
                acc[mi][ni][2] += f1.x; acc[mi][ni][3] += f1.y;
            }
        }
    }

    if (!DO_LN) {
        // plain write (fp16)
#pragma unroll
        for (int mi = 0; mi < 2; mi++)
#pragma unroll
            for (int ni = 0; ni < 8; ni++) {
                int r0 = brow + wm + mi * 16 + g;
                int r1 = r0 + 8;
                int c0 = bcol + wn + ni * 8 + tg * 2;
                *(__half2*)&outh[(size_t)r0 * ostride + c0] =
                    __floats2half2_rn(acc[mi][ni][0], acc[mi][ni][1]);
                *(__half2*)&outh[(size_t)r1 * ostride + c0] =
                    __floats2half2_rn(acc[mi][ni][2], acc[mi][ni][3]);
            }
        return;
    }

    // ---- fused LayerNorm over the 512-wide rows ----
    __syncthreads();                      // mainloop smem reads done everywhere
    float* sred  = (float*)smem;          // [64][8][2] partials
    float* stats = sred + 64 * 8 * 2;     // [64][2] mean/rstd

#pragma unroll
    for (int mi = 0; mi < 2; mi++) {
        float s0 = 0.f, q0 = 0.f, s1 = 0.f, q1 = 0.f;
#pragma unroll
        for (int ni = 0; ni < 8; ni++) {
            float a0 = acc[mi][ni][0], a1 = acc[mi][ni][1];
            float a2 = acc[mi][ni][2], a3 = acc[mi][ni][3];
            s0 += a0 + a1; q0 += a0 * a0 + a1 * a1;
            s1 += a2 + a3; q1 += a2 * a2 + a3 * a3;
        }
#pragma unroll
        for (int m = 1; m <= 2; m <<= 1) {
            s0 += __shfl_xor_sync(0xFFFFFFFFu, s0, m);
            q0 += __shfl_xor_sync(0xFFFFFFFFu, q0, m);
            s1 += __shfl_xor_sync(0xFFFFFFFFu, s1, m);
            q1 += __shfl_xor_sync(0xFFFFFFFFu, q1, m);
        }
        if (tg == 0) {
            int row0 = wm + mi * 16 + g;
            int row1 = row0 + 8;
            sred[(row0 * 8 + wn8) * 2 + 0] = s0;
            sred[(row0 * 8 + wn8) * 2 + 1] = q0;
            sred[(row1 * 8 + wn8) * 2 + 0] = s1;
            sred[(row1 * 8 + wn8) * 2 + 1] = q1;
        }
    }
    __syncthreads();
    if (t < 64) {
        float s = 0.f, q = 0.f;
#pragma unroll
        for (int w8 = 0; w8 < 8; w8++) {
            s += sred[(t * 8 + w8) * 2 + 0];
            q += sred[(t * 8 + w8) * 2 + 1];
        }
        float mean = s * (1.f / BN);
        float var  = q * (1.f / BN) - mean * mean;
        stats[t * 2 + 0] = mean;
        stats[t * 2 + 1] = rsqrtf(var + 1e-5f);
    }
    __syncthreads();

#pragma unroll
    for (int mi = 0; mi < 2; mi++) {
        int row0 = wm + mi * 16 + g;
        int row1 = row0 + 8;
        float m0 = stats[row0 * 2], r0s = stats[row0 * 2 + 1];
        float m1 = stats[row1 * 2], r1s = stats[row1 * 2 + 1];
        int gr0 = brow + row0, gr1 = brow + row1;
#pragma unroll
        for (int ni = 0; ni < 8; ni++) {
            int c0 = wn + ni * 8 + tg * 2;
            float ga0 = gam[c0], ga1 = gam[c0 + 1];
            float be0 = bet[c0], be1 = bet[c0 + 1];
            float y00 = (acc[mi][ni][0] - m0) * r0s * ga0 + be0;
            float y01 = (acc[mi][ni][1] - m0) * r0s * ga1 + be1;
            float y10 = (acc[mi][ni][2] - m1) * r1s * ga0 + be0;
            float y11 = (acc[mi][ni][3] - m1) * r1s * ga1 + be1;
            if (outh) {
                *(__half2*)&outh[(size_t)gr0 * ostride + c0] = __floats2half2_rn(y00, y01);
                *(__half2*)&outh[(size_t)gr1 * ostride + c0] = __floats2half2_rn(y10, y11);
            } else {
                float* o0 = outf + (size_t)gr0 * ldo + coloff + c0;
                float* o1 = outf + (size_t)gr1 * ldo + coloff + c0;
                o0[0] = y00; o0[1] = y01;
                o1[0] = y10; o1[1] = y11;
            }
        }
    }
}

// ------------------------------- launch ---------------------------------------
extern "C" void kernel_launch(void* const* d_in, const int* in_sizes, int n_in,
                              void* d_out, int out_size) {
    const float* a_in_w[2]  = { (const float*)d_in[2], (const float*)d_in[6] };
    const float* a_in_b[2]  = { (const float*)d_in[3], (const float*)d_in[7] };
    const float* a_out_w[2] = { (const float*)d_in[4], (const float*)d_in[8] };
    const float* a_out_b[2] = { (const float*)d_in[5], (const float*)d_in[9] };
    const float* lnA_g[2] = { (const float*)d_in[10], (const float*)d_in[12] };
    const float* lnA_b[2] = { (const float*)d_in[11], (const float*)d_in[13] };
    const float* lnB_g[2] = { (const float*)d_in[14], (const float*)d_in[16] };
    const float* lnB_b[2] = { (const float*)d_in[15], (const float*)d_in[17] };
    const float* f_w1[2] = { (const float*)d_in[18], (const float*)d_in[22] };
    const float* f_b1[2] = { (const float*)d_in[19], (const float*)d_in[23] };
    const float* f_w2[2] = { (const float*)d_in[20], (const float*)d_in[24] };
    const float* f_b2[2] = { (const float*)d_in[21], (const float*)d_in[25] };
    float* out = (float*)d_out;

    __half *xh[2], *hb, *ub, *wc, *w1h, *w2h;
    float *cbuf;
    cudaGetSymbolAddress((void**)&xh[0], g_xh0);
    cudaGetSymbolAddress((void**)&xh[1], g_xh1);
    cudaGetSymbolAddress((void**)&hb,   g_h);
    cudaGetSymbolAddress((void**)&ub,   g_u);
    cudaGetSymbolAddress((void**)&wc,   g_wc);
    cudaGetSymbolAddress((void**)&cbuf, g_c);
    cudaGetSymbolAddress((void**)&w1h,  g_w1h);
    cudaGetSymbolAddress((void**)&w2h,  g_w2h);

    __half* h[2] = { hb, hb + (size_t)MROWS * EDIM };
    __half* u[2] = { ub, ub + (size_t)MROWS * FFDIM };

    cudaFuncSetAttribute(k_gemm_w<EDIM, 1>,
                         cudaFuncAttributeMaxDynamicSharedMemorySize, GEMM_SMEM);
    cudaFuncSetAttribute(k_gemm_w<EDIM, 0>,
                         cudaFuncAttributeMaxDynamicSharedMemorySize, GEMM_SMEM);
    cudaFuncSetAttribute(k_gemm_w<FFDIM, 1>,
                         cudaFuncAttributeMaxDynamicSharedMemorySize, GEMM_SMEM);

    static cudaStream_t br[2] = {nullptr, nullptr};
    static cudaEvent_t evRoot = nullptr, evAct = nullptr, evD[2] = {nullptr, nullptr};
    if (!br[0]) {
        cudaStreamCreateWithFlags(&br[0], cudaStreamNonBlocking);
        cudaStreamCreateWithFlags(&br[1], cudaStreamNonBlocking);
        cudaEventCreateWithFlags(&evRoot, cudaEventDisableTiming);
        cudaEventCreateWithFlags(&evAct,  cudaEventDisableTiming);
        cudaEventCreateWithFlags(&evD[0], cudaEventDisableTiming);
        cudaEventCreateWithFlags(&evD[1], cudaEventDisableTiming);
    }

    const int NXE = MROWS * EDIM;

    // fork: branches start with weight prep
    cudaEventRecord(evRoot, 0);
    cudaStreamWaitEvent(br[0], evRoot, 0);
    cudaStreamWaitEvent(br[1], evRoot, 0);

    // main stream: activation converts (overlap branches' weight prep)
    k_f2h<<<NXE / 1024, 256>>>((const float*)d_in[0], xh[0], NXE);
    k_f2h<<<NXE / 1024, 256>>>((const float*)d_in[1], xh[1], NXE);
    cudaEventRecord(evAct, 0);

    dim3 g1(1, MROWS / BM);   // (1, 512) — N=512
    dim3 g2(2, MROWS / BM);   // (2, 512) — N=1024

    for (int s = 0; s < 2; s++) {
        cudaStream_t st = br[s];
        __half* w1s = w1h + (size_t)s * FFDIM * EDIM;
        __half* w2s = w2h + (size_t)s * EDIM * FFDIM;
        __half* wcs = wc  + (size_t)s * EDIM * EDIM;
        float*  ccs = cbuf + s * EDIM;

        // weight prep (independent of activations)
        k_f2h<<<(FFDIM * EDIM) / 1024, 256, 0, st>>>(f_w1[s], w1s, FFDIM * EDIM);
        k_f2h<<<(EDIM * FFDIM) / 1024, 256, 0, st>>>(f_w2[s], w2s, EDIM * FFDIM);
        k_fold<<<EDIM, EDIM, 0, st>>>(a_out_w[s], a_in_w[s] + 2 * EDIM * EDIM, wcs);
        k_foldc<<<2, 256, 0, st>>>(a_out_w[s], a_out_b[s], a_in_b[s] + 2 * EDIM, ccs);

        cudaStreamWaitEvent(st, evAct, 0);

        // h = LN(x_s + xh[1-s] @ Wc^T + c)   [fused GEMM+LN]
        k_gemm_w<EDIM, 1><<<g1, 512, GEMM_SMEM, st>>>(
            xh[1 - s], wcs, ccs, xh[s], lnA_g[s], lnA_b[s],
            h[s], EDIM, nullptr, 0, 0, 0);
        // u = relu(h @ w1^T + b1)
        k_gemm_w<EDIM, 0><<<g2, 512, GEMM_SMEM, st>>>(
            h[s], w1s, f_b1[s], nullptr, nullptr, nullptr,
            u[s], FFDIM, nullptr, 0, 0, 1);
        // out[:, s*512:(s+1)*512] = LN(h + u @ w2^T + b2)   [fused GEMM+LN]
        k_gemm_w<FFDIM, 1><<<g1, 512, GEMM_SMEM, st>>>(
            u[s], w2s, f_b2[s], h[s], lnB_g[s], lnB_b[s],
            nullptr, 0, out, 2 * EDIM, s * EDIM, 0);

        cudaEventRecord(evD[s], st);
    }

    cudaStreamWaitEvent(0, evD[0], 0);
    cudaStreamWaitEvent(0, evD[1], 0);
}

// round 16
// speedup vs baseline: 1.1802x; 1.1802x over previous
#include <cuda_runtime.h>
#include <cuda_fp16.h>
#include <cstdint>

// ----------------------------------------------------------------------------
// CrossAttention_30056181138117 on GB300 (sm_103a) — round 16
//
// (harness lowers through family-generic compute_103 PTX -> tcgen05 rejected;
// tuned legacy-HMMA path)
//
// Seq-len-1 attention => softmax == 1 => attn out == V projection, folded:
//   att_s = x_other @ Wc_s^T + c_s,  Wc_s = out_w_s @ wv_s
// Per stream: h = LN(x + att); u = relu(h@w1^T+b1); o = LN(h + u@w2^T+b2)
//
// Round-16 = round-8 winner (783us; all kernels byte-identical) with the
// activation converts moved onto the TWO existing branch streams (branch s
// converts its own A-operand xh[1-s] first, then weight prep, then waits on
// the other branch's convert for its residual). No extra streams (round-15's
// 4-stream topology leaked a 2MB graph-upload buffer and was not faster).
// ----------------------------------------------------------------------------

#define MROWS 32768
#define EDIM  512
#define FFDIM 1024

#define BM 128
#define BN 128
#define BK 32
#define NSTAGE 3
#define LDS 40                          // halfs per smem row (80B, 16B-aligned)
#define ASTG (BM * LDS)
#define WSTG (BN * LDS)
#define GEMM_SMEM (NSTAGE * (ASTG + WSTG) * 2)   // 61440 bytes

// ------------------------- device scratch (static, no allocs) ---------------
__device__ __half g_xh0[MROWS * EDIM];
__device__ __half g_xh1[MROWS * EDIM];
__device__ __half g_h  [2][MROWS * EDIM];
__device__ __half g_u  [2][MROWS * FFDIM];
__device__ __half g_t16[2][MROWS * EDIM];
__device__ __half g_wc [2 * EDIM * EDIM];
__device__ float  g_c  [2 * EDIM];
__device__ __half g_w1h[2 * FFDIM * EDIM];
__device__ __half g_w2h[2 * EDIM * FFDIM];

// ------------------------- helpers -------------------------------------------
__device__ __forceinline__ void cp_async16(uint32_t dst, const void* src) {
    asm volatile("cp.async.cg.shared.global [%0], [%1], 16;\n" :: "r"(dst), "l"(src));
}
__device__ __forceinline__ void ldsm_x4(uint32_t& r0, uint32_t& r1,
                                        uint32_t& r2, uint32_t& r3, uint32_t addr) {
    asm volatile("ldmatrix.sync.aligned.m8n8.x4.shared.b16 {%0,%1,%2,%3}, [%4];"
                 : "=r"(r0), "=r"(r1), "=r"(r2), "=r"(r3) : "r"(addr));
}

// ------------------------- small kernels -------------------------------------
__global__ void k_f2h(const float* __restrict__ src, __half* __restrict__ dst, int n) {
    int i = (blockIdx.x * blockDim.x + threadIdx.x) * 4;
    if (i >= n) return;
    float4 v = *(const float4*)(src + i);
    __half2* d = (__half2*)(dst + i);
    d[0] = __floats2half2_rn(v.x, v.y);
    d[1] = __floats2half2_rn(v.z, v.w);
}

__global__ void k_fold(const float* __restrict__ out_w,
                       const float* __restrict__ wv,
                       __half* __restrict__ wc) {
    __shared__ float srow[EDIM];
    int i = blockIdx.x, k = threadIdx.x;
    srow[k] = out_w[i * EDIM + k];
    __syncthreads();
    float acc = 0.f;
#pragma unroll 4
    for (int j = 0; j < EDIM; j++) acc = fmaf(srow[j], wv[j * EDIM + k], acc);
    wc[i * EDIM + k] = __float2half(acc);
}

__global__ void k_foldc(const float* __restrict__ out_w,
                        const float* __restrict__ out_b,
                        const float* __restrict__ bv,
                        float* __restrict__ c) {
    int i = blockIdx.x * blockDim.x + threadIdx.x;
    if (i >= EDIM) return;
    float acc = out_b[i];
    for (int j = 0; j < EDIM; j++) acc = fmaf(out_w[i * EDIM + j], bv[j], acc);
    c[i] = acc;
}

// ------------------------- fp16 HMMA GEMM (round-8 body, unchanged) -----------
template <int K>
__global__ __launch_bounds__(256, 2) void k_gemm(
    const __half* __restrict__ A, const __half* __restrict__ W,
    const float* __restrict__ bias,
    const __half* __restrict__ resh,
    __half* __restrict__ outh,
    int N, int relu)
{
    constexpr int NT = K / BK;
    extern __shared__ __half smem[];
    __half* Asm = smem;
    __half* Wsm = smem + NSTAGE * ASTG;
    const uint32_t as_u = (uint32_t)__cvta_generic_to_shared(Asm);
    const uint32_t ws_u = (uint32_t)__cvta_generic_to_shared(Wsm);

    const int t = threadIdx.x;
    const int warp = t >> 5, lane = t & 31;
    const int g = lane >> 2, tg = lane & 3;
    const int brow = blockIdx.y * BM;
    const int bcol = blockIdx.x * BN;
    const int wm = (warp >> 1) * 32;
    const int wn = (warp & 1) * 64;

    const int lr = t >> 2;
    const int lc = (t & 3) * 8;
    const __half* Ag = A + (size_t)(brow + lr) * K + lc;
    const __half* Wg = W + (size_t)(bcol + lr) * K + lc;

    const int arow = lane & 15;
    const int acol = (lane & 16) >> 1;
    const int browl = (lane & 7) + ((lane & 16) >> 1);
    const int bcoll = lane & 8;

    float acc[2][8][4];
#pragma unroll
    for (int a = 0; a < 2; a++)
#pragma unroll
        for (int b = 0; b < 8; b++)
#pragma unroll
            for (int c = 0; c < 4; c++) acc[a][b][c] = 0.f;

    auto load_stage = [&](int i, int slot) {
        const int ko = i * BK;
        const uint32_t as = as_u + slot * ASTG * 2;
        const uint32_t ws = ws_u + slot * WSTG * 2;
        cp_async16(as + (lr * LDS + lc) * 2,        Ag + ko);
        cp_async16(as + ((lr + 64) * LDS + lc) * 2, Ag + ko + (size_t)64 * K);
        cp_async16(ws + (lr * LDS + lc) * 2,        Wg + ko);
        cp_async16(ws + ((lr + 64) * LDS + lc) * 2, Wg + ko + (size_t)64 * K);
        asm volatile("cp.async.commit_group;\n");
    };

    load_stage(0, 0);
    load_stage(1, 1);

    for (int i = 0; i < NT; i++) {
        if (i + 1 < NT) asm volatile("cp.async.wait_group 1;\n");
        else            asm volatile("cp.async.wait_group 0;\n");
        __syncthreads();   // single barrier per K-iter

        if (i + 2 < NT) load_stage(i + 2, (i + 2) % NSTAGE);

        const int s = i % NSTAGE;
        const uint32_t as = as_u + s * ASTG * 2;
        const uint32_t ws = ws_u + s * WSTG * 2;

#pragma unroll
        for (int kk = 0; kk < BK; kk += 16) {
            uint32_t ra[2][4], rb[8][2];
#pragma unroll
            for (int mi = 0; mi < 2; mi++)
                ldsm_x4(ra[mi][0], ra[mi][1], ra[mi][2], ra[mi][3],
                        as + ((wm + mi * 16 + arow) * LDS + kk + acol) * 2);
#pragma unroll
            for (int np = 0; np < 4; np++)
                ldsm_x4(rb[2 * np][0], rb[2 * np][1], rb[2 * np + 1][0], rb[2 * np + 1][1],
                        ws + ((wn + np * 16 + browl) * LDS + kk + bcoll) * 2);
#pragma unroll
            for (int mi = 0; mi < 2; mi++)
#pragma unroll
                for (int ni = 0; ni < 8; ni++)
                    asm volatile(
                        "mma.sync.aligned.m16n8k16.row.col.f32.f16.f16.f32 "
                        "{%0,%1,%2,%3}, {%4,%5,%6,%7}, {%8,%9}, {%0,%1,%2,%3};"
                        : "+f"(acc[mi][ni][0]), "+f"(acc[mi][ni][1]),
                          "+f"(acc[mi][ni][2]), "+f"(acc[mi][ni][3])
                        : "r"(ra[mi][0]), "r"(ra[mi][1]), "r"(ra[mi][2]), "r"(ra[mi][3]),
                          "r"(rb[ni][0]), "r"(rb[ni][1]));
        }
    }

#pragma unroll
    for (int mi = 0; mi < 2; mi++) {
#pragma unroll
        for (int ni = 0; ni < 8; ni++) {
            int r0 = brow + wm + mi * 16 + g;
            int r1 = r0 + 8;
            int c0 = bcol + wn + ni * 8 + tg * 2;
            float v0 = acc[mi][ni][0], v1 = acc[mi][ni][1];
            float v2 = acc[mi][ni][2], v3 = acc[mi][ni][3];
            float b0 = bias[c0], b1 = bias[c0 + 1];
            v0 += b0; v1 += b1; v2 += b0; v3 += b1;
            if (relu) {
                v0 = fmaxf(v0, 0.f); v1 = fmaxf(v1, 0.f);
                v2 = fmaxf(v2, 0.f); v3 = fmaxf(v3, 0.f);
            }
            if (resh) {
                float2 f0 = __half22float2(*(const __half2*)&resh[(size_t)r0 * EDIM + c0]);
                float2 f1 = __half22float2(*(const __half2*)&resh[(size_t)r1 * EDIM + c0]);
                v0 += f0.x; v1 += f0.y; v2 += f1.x; v3 += f1.y;
            }
            *(__half2*)&outh[(size_t)r0 * N + c0] = __floats2half2_rn(v0, v1);
            *(__half2*)&outh[(size_t)r1 * N + c0] = __floats2half2_rn(v2, v3);
        }
    }
}

// ------------------------- row LayerNorm (E=512, fp16 in) ---------------------
__global__ void k_ln(const __half* __restrict__ x,
                     const float* __restrict__ gam, const float* __restrict__ bet,
                     __half* __restrict__ outh, float* __restrict__ outf,
                     int ld_out, int coloff)
{
    int row = blockIdx.x;
    int t = threadIdx.x;  // 128 threads
    const __half2* xr = (const __half2*)(x + (size_t)row * EDIM);
    float2 v[2];
    float s = 0.f, sq = 0.f;
#pragma unroll
    for (int i = 0; i < 2; i++) {
        v[i] = __half22float2(xr[t + i * 128]);
        s  += v[i].x + v[i].y;
        sq += v[i].x * v[i].x + v[i].y * v[i].y;
    }
#pragma unroll
    for (int o = 16; o > 0; o >>= 1) {
        s  += __shfl_xor_sync(0xFFFFFFFFu, s, o);
        sq += __shfl_xor_sync(0xFFFFFFFFu, sq, o);
    }
    __shared__ float ss[4], ssq[4];
    int w = t >> 5, l = t & 31;
    if (l == 0) { ss[w] = s; ssq[w] = sq; }
    __syncthreads();
    s  = ss[0] + ss[1] + ss[2] + ss[3];
    sq = ssq[0] + ssq[1] + ssq[2] + ssq[3];
    float mean = s * (1.f / EDIM);
    float var  = sq * (1.f / EDIM) - mean * mean;
    float rstd = rsqrtf(var + 1e-5f);
#pragma unroll
    for (int i = 0; i < 2; i++) {
        int c = 2 * (t + i * 128);
        float y0 = (v[i].x - mean) * rstd * gam[c]     + bet[c];
        float y1 = (v[i].y - mean) * rstd * gam[c + 1] + bet[c + 1];
        if (outh) *(__half2*)&outh[(size_t)row * EDIM + c] = __floats2half2_rn(y0, y1);
        if (outf) {
            outf[(size_t)row * ld_out + coloff + c]     = y0;
            outf[(size_t)row * ld_out + coloff + c + 1] = y1;
        }
    }
}

// ------------------------------- launch ---------------------------------------
extern "C" void kernel_launch(void* const* d_in, const int* in_sizes, int n_in,
                              void* d_out, int out_size) {
    const float* xin[2] = { (const float*)d_in[0], (const float*)d_in[1] };
    const float* a_in_w[2]  = { (const float*)d_in[2], (const float*)d_in[6] };
    const float* a_in_b[2]  = { (const float*)d_in[3], (const float*)d_in[7] };
    const float* a_out_w[2] = { (const float*)d_in[4], (const float*)d_in[8] };
    const float* a_out_b[2] = { (const float*)d_in[5], (const float*)d_in[9] };
    const float* lnA_g[2] = { (const float*)d_in[10], (const float*)d_in[12] };
    const float* lnA_b[2] = { (const float*)d_in[11], (const float*)d_in[13] };
    const float* lnB_g[2] = { (const float*)d_in[14], (const float*)d_in[16] };
    const float* lnB_b[2] = { (const float*)d_in[15], (const float*)d_in[17] };
    const float* f_w1[2] = { (const float*)d_in[18], (const float*)d_in[22] };
    const float* f_b1[2] = { (const float*)d_in[19], (const float*)d_in[23] };
    const float* f_w2[2] = { (const float*)d_in[20], (const float*)d_in[24] };
    const float* f_b2[2] = { (const float*)d_in[21], (const float*)d_in[25] };
    float* out = (float*)d_out;

    __half *xh[2], *hb, *ub, *tb, *wc, *w1h, *w2h;
    float *cbuf;
    cudaGetSymbolAddress((void**)&xh[0], g_xh0);
    cudaGetSymbolAddress((void**)&xh[1], g_xh1);
    cudaGetSymbolAddress((void**)&hb,   g_h);
    cudaGetSymbolAddress((void**)&ub,   g_u);
    cudaGetSymbolAddress((void**)&tb,   g_t16);
    cudaGetSymbolAddress((void**)&wc,   g_wc);
    cudaGetSymbolAddress((void**)&cbuf, g_c);
    cudaGetSymbolAddress((void**)&w1h,  g_w1h);
    cudaGetSymbolAddress((void**)&w2h,  g_w2h);

    __half* h [2] = { hb, hb + (size_t)MROWS * EDIM };
    __half* u [2] = { ub, ub + (size_t)MROWS * FFDIM };
    __half* tt[2] = { tb, tb + (size_t)MROWS * EDIM };

    cudaFuncSetAttribute(k_gemm<EDIM>,
                         cudaFuncAttributeMaxDynamicSharedMemorySize, GEMM_SMEM);
    cudaFuncSetAttribute(k_gemm<FFDIM>,
                         cudaFuncAttributeMaxDynamicSharedMemorySize, GEMM_SMEM);

    // TWO streams only (round-15's 4-stream topology leaked graph-upload mem)
    static cudaStream_t br[2] = {nullptr, nullptr};
    static cudaEvent_t evRoot = nullptr, evX[2] = {nullptr, nullptr},
                       evD[2] = {nullptr, nullptr};
    if (!br[0]) {
        cudaStreamCreateWithFlags(&br[0], cudaStreamNonBlocking);
        cudaStreamCreateWithFlags(&br[1], cudaStreamNonBlocking);
        cudaEventCreateWithFlags(&evRoot, cudaEventDisableTiming);
        cudaEventCreateWithFlags(&evX[0], cudaEventDisableTiming);
        cudaEventCreateWithFlags(&evX[1], cudaEventDisableTiming);
        cudaEventCreateWithFlags(&evD[0], cudaEventDisableTiming);
        cudaEventCreateWithFlags(&evD[1], cudaEventDisableTiming);
    }

    const int NXE = MROWS * EDIM;

    // fork
    cudaEventRecord(evRoot, 0);
    cudaStreamWaitEvent(br[0], evRoot, 0);
    cudaStreamWaitEvent(br[1], evRoot, 0);

    // branch s converts its own A operand xh[1-s] FIRST (the two converts run
    // concurrently), recording availability for the other branch's residual.
    for (int s = 0; s < 2; s++) {
        k_f2h<<<NXE / 1024, 256, 0, br[s]>>>(xin[1 - s], xh[1 - s], NXE);
        cudaEventRecord(evX[1 - s], br[s]);
    }

    dim3 gE(EDIM / BN, MROWS / BM);    // (4, 256)
    dim3 gF(FFDIM / BN, MROWS / BM);   // (8, 256)

    for (int s = 0; s < 2; s++) {
        cudaStream_t st = br[s];
        __half* w1s = w1h + (size_t)s * FFDIM * EDIM;
        __half* w2s = w2h + (size_t)s * EDIM * FFDIM;
        __half* wcs = wc  + (size_t)s * EDIM * EDIM;
        float*  ccs = cbuf + s * EDIM;

        // weight prep on the same stream (covers the other branch's convert)
        k_f2h<<<(FFDIM * EDIM) / 1024, 256, 0, st>>>(f_w1[s], w1s, FFDIM * EDIM);
        k_f2h<<<(EDIM * FFDIM) / 1024, 256, 0, st>>>(f_w2[s], w2s, EDIM * FFDIM);
        k_fold<<<EDIM, EDIM, 0, st>>>(a_out_w[s], a_in_w[s] + 2 * EDIM * EDIM, wcs);
        k_foldc<<<2, 256, 0, st>>>(a_out_w[s], a_out_b[s], a_in_b[s] + 2 * EDIM, ccs);

        // residual xh[s] was converted by the OTHER branch
        cudaStreamWaitEvent(st, evX[s], 0);

        const __half* kv = xh[1 - s];
        // t = x_s + kv @ Wc^T + c
        k_gemm<EDIM><<<gE, 256, GEMM_SMEM, st>>>(kv, wcs, ccs, xh[s], tt[s], EDIM, 0);
        // h = LN(t)
        k_ln<<<MROWS, 128, 0, st>>>(tt[s], lnA_g[s], lnA_b[s], h[s], nullptr, 0, 0);
        // u = relu(h @ w1^T + b1)
        k_gemm<EDIM><<<gF, 256, GEMM_SMEM, st>>>(h[s], w1s, f_b1[s], nullptr, u[s], FFDIM, 1);
        // t = h + u @ w2^T + b2
        k_gemm<FFDIM><<<gE, 256, GEMM_SMEM, st>>>(u[s], w2s, f_b2[s], h[s], tt[s], EDIM, 0);
        // out[:, s*512:(s+1)*512] = LN(t)
        k_ln<<<MROWS, 128, 0, st>>>(tt[s], lnB_g[s], lnB_b[s], nullptr, out, 2 * EDIM, s * EDIM);

        cudaEventRecord(evD[s], st);
    }

    cudaStreamWaitEvent(0, evD[0], 0);
    cudaStreamWaitEvent(0, evD[1], 0);
}